// round 7
// baseline (speedup 1.0000x reference)
#include <cuda_runtime.h>
#include <cstdint>

// Problem constants
#define BATCH 128
#define TT    512
#define NBLK  128      // persistent grid (all co-resident)
#define NTHR  256      // 8 warps, warp tile 16x32 on CTA tile 64x64, k-chunk 128
#define SP    136      // smem row pitch in words; 136 % 32 == 8 -> conflict-free LDS.64
#define AW    (64 * SP)        // words of A region per stage (8704)
#define SW    (2 * AW)         // words per stage (A + B)
#define STAGE_B (SW * 4)       // bytes per stage (69632)
#define NSTAGE 3

// ---------------- device scratch (static, allocation-free) ----------------
__device__ __align__(16) float g_z[BATCH * 1024];        // fc output (tf32, k-permuted)
__device__ __align__(16) float g_h1[2][BATCH * 1024];    // layer-0 hidden
__device__ __align__(16) float g_h2[2][BATCH * 1024];    // layer-1 hidden
__device__ __align__(16) float g_wpack[4u * 64u * 8u * 8192u]; // packed tf32 weights, 64MB
__device__ unsigned g_bar_count;
__device__ volatile unsigned g_bar_gen;

// perm of low-3 bits: puts (k, k+4) adjacent -> LDS.64 fragment pairs
__device__ __host__ __forceinline__ int perm8(int i) { return ((i & 3) << 1) | ((i >> 2) & 1); }

// ---------------- helpers ----------------
__device__ __forceinline__ unsigned f2tf32(float x) {
    unsigned r;
    asm("cvt.rna.tf32.f32 %0, %1;" : "=r"(r) : "f"(x));
    return r;
}
__device__ __forceinline__ float rtf(float x) { return __uint_as_float(f2tf32(x)); }

__device__ __forceinline__ void mma_tf32(float c[4], unsigned a0, unsigned a1,
                                         unsigned a2, unsigned a3,
                                         unsigned b0, unsigned b1) {
    asm volatile(
        "mma.sync.aligned.m16n8k8.row.col.f32.tf32.tf32.f32 "
        "{%0,%1,%2,%3}, {%4,%5,%6,%7}, {%8,%9}, {%0,%1,%2,%3};"
        : "+f"(c[0]), "+f"(c[1]), "+f"(c[2]), "+f"(c[3])
        : "r"(a0), "r"(a1), "r"(a2), "r"(a3), "r"(b0), "r"(b1));
}

__device__ __forceinline__ void cp16(unsigned dst, const void* src) {
    asm volatile("cp.async.cg.shared.global [%0], [%1], 16;\n" :: "r"(dst), "l"(src));
}
#define CP_COMMIT() asm volatile("cp.async.commit_group;\n" ::: "memory")
#define CP_WAIT1()  asm volatile("cp.async.wait_group 1;\n" ::: "memory")

__device__ __forceinline__ float sigf(float x) { return 1.0f / (1.0f + __expf(-x)); }
__device__ __forceinline__ float tanh_fast(float x) {
    float e = __expf(2.0f * x);
    return 1.0f - 2.0f / (e + 1.0f);
}

// ---------------- software grid barrier ----------------
__device__ __forceinline__ void grid_barrier() {
    __threadfence();
    __syncthreads();
    if (threadIdx.x == 0) {
        unsigned gen = g_bar_gen;
        if (atomicAdd(&g_bar_count, 1u) == NBLK - 1) {
            *(volatile unsigned*)&g_bar_count = 0;
            __threadfence();
            g_bar_gen = gen + 1;
        } else {
            while (g_bar_gen == gen) {}
        }
        __threadfence();
    }
    __syncthreads();
}

// ---------------- init ----------------
__global__ void init_zero_kernel() {
    int idx = blockIdx.x * 256 + threadIdx.x;
    if (idx < BATCH * 1024 * 2) {
        (&g_h1[0][0])[idx] = 0.0f;
        (&g_h2[0][0])[idx] = 0.0f;
    }
    if (idx == 0) { g_bar_count = 0; g_bar_gen = 0; }
}

// ---------------- weight pre-pack: tf32, k128-chunk-major, k-permuted ----------------
// wpack[mat][nb][kc8][rr64][kk128]; rr: gate=(rr>>3)&3, jloc=(rr&7)+((rr>>5)<<3)
__global__ void pack_kernel(const float* __restrict__ W0, const float* __restrict__ W1,
                            const float* __restrict__ W2, const float* __restrict__ W3) {
    int idx = blockIdx.x * 256 + threadIdx.x;   // 65536 blocks -> 16777216
    int kk  = idx & 127;
    int rr  = (idx >> 7) & 63;
    int kc  = (idx >> 13) & 7;
    int nb  = (idx >> 16) & 63;
    int mat = idx >> 22;
    const float* W = (mat == 0) ? W0 : (mat == 1) ? W1 : (mat == 2) ? W2 : W3;
    int gate = (rr >> 3) & 3;
    int jloc = (rr & 7) + ((rr >> 5) << 3);
    int srow = gate * 1024 + nb * 16 + jloc;
    float v = W[srow * 1024 + kc * 128 + kk];
    int kkp = (kk & ~7) | perm8(kk & 7);
    g_wpack[(((size_t)(mat * 64 + nb) * 8 + kc) << 13) + rr * 128 + kkp] = rtf(v);
}

// ---------------- fc: z = x @ fc_w^T + fc_b (tf32, k-permuted) ----------------
__global__ void fc_kernel(const float* __restrict__ x, const float* __restrict__ fcw,
                          const float* __restrict__ fcb) {
    int idx = blockIdx.x * 256 + threadIdx.x;
    int b = idx >> 10, i = idx & 1023;
    const float4* xr = reinterpret_cast<const float4*>(x + b * 256);
    const float4* wr = reinterpret_cast<const float4*>(fcw + i * 256);
    float s = fcb[i];
    #pragma unroll 8
    for (int o = 0; o < 64; o++) {
        float4 xv = __ldg(xr + o), wv = __ldg(wr + o);
        s += xv.x * wv.x + xv.y * wv.y + xv.z * wv.z + xv.w * wv.w;
    }
    int ip = (i & ~7) | perm8(i & 7);
    g_z[b * 1024 + ip] = rtf(s);
}

// ---------------- tile compute: 64x64 CTA tile, k=128, warp tile 16x32 ----------------
__device__ __forceinline__ void tile_compute(const unsigned* __restrict__ as,
                                             const unsigned* __restrict__ bs,
                                             float acc[4][4], int wm, int wn,
                                             int grp, int tig) {
    const unsigned* pa = as + (wm * 16 + grp) * SP + 2 * tig;
    const unsigned* pb = bs + (wn * 32 + grp) * SP + 2 * tig;

    uint2 a0 = *(const uint2*)pa;
    uint2 a1 = *(const uint2*)(pa + 8 * SP);
    uint2 b0 = *(const uint2*)pb;
    uint2 b1 = *(const uint2*)(pb + 8 * SP);
    uint2 b2 = *(const uint2*)(pb + 16 * SP);
    uint2 b3 = *(const uint2*)(pb + 24 * SP);

    #pragma unroll
    for (int k8 = 0; k8 < 16; k8++) {
        uint2 na0, na1, nb0, nb1, nb2, nb3;
        if (k8 < 15) {
            const unsigned* qa = pa + (k8 + 1) * 8;
            const unsigned* qb = pb + (k8 + 1) * 8;
            na0 = *(const uint2*)qa;
            na1 = *(const uint2*)(qa + 8 * SP);
            nb0 = *(const uint2*)qb;
            nb1 = *(const uint2*)(qb + 8 * SP);
            nb2 = *(const uint2*)(qb + 16 * SP);
            nb3 = *(const uint2*)(qb + 24 * SP);
        }
        mma_tf32(acc[0], a0.x, a1.x, a0.y, a1.y, b0.x, b0.y);
        mma_tf32(acc[1], a0.x, a1.x, a0.y, a1.y, b1.x, b1.y);
        mma_tf32(acc[2], a0.x, a1.x, a0.y, a1.y, b2.x, b2.y);
        mma_tf32(acc[3], a0.x, a1.x, a0.y, a1.y, b3.x, b3.y);
        if (k8 < 15) {
            a0 = na0; a1 = na1; b0 = nb0; b1 = nb1; b2 = nb2; b3 = nb3;
        }
    }
}

// ---------------- GEMM phase: acc[64x64] += A[64 x 128*nIter] @ Bpacked^T ----------------
// A slab: A0 for chunks s<8, A1 for s>=8 (layer-1 concat). B likewise.
__device__ __forceinline__ void gemm_phase(
    float acc[4][4],
    const float* __restrict__ A0, const float* __restrict__ A1,
    const float* __restrict__ B0, const float* __restrict__ B1,
    int nIter, int mb, const unsigned* shp, unsigned sb,
    int tid, int wm, int wn, int grp, int tig)
{
    #pragma unroll
    for (int j = 0; j < 4; j++)
        #pragma unroll
        for (int r = 0; r < 4; r++) acc[j][r] = 0.0f;

    const int lrow = tid >> 5;        // 0..7, +8 per round
    const int c16  = tid & 31;        // uint4 column 0..31 (k128 = 32 x 16B)

    #define ISSUE(s) do {                                                       \
        unsigned sa_ = sb + (unsigned)((s) % 3) * STAGE_B;                      \
        const float* A_  = ((s) < 8) ? A0 : A1;                                 \
        const float* Bt_ = (((s) < 8) ? B0 : B1) + (size_t)((s) & 7) * 8192;    \
        int koff_ = ((s) & 7) << 7;                                             \
        _Pragma("unroll")                                                       \
        for (int v = 0; v < 8; v++) {                                           \
            int row = lrow + v * 8;                                             \
            cp16(sa_ + (row * SP + c16 * 4) * 4,                                \
                 A_ + (mb * 64 + row) * 1024 + koff_ + c16 * 4);                \
            cp16(sa_ + (AW + row * SP + c16 * 4) * 4,                           \
                 Bt_ + row * 128 + c16 * 4);                                    \
        }                                                                       \
    } while (0)

    ISSUE(0); CP_COMMIT();
    ISSUE(1); CP_COMMIT();

    for (int it = 0; it < nIter; it++) {
        CP_WAIT1();
        __syncthreads();
        const unsigned* st = shp + (it % 3) * SW;
        tile_compute(st, st + AW, acc, wm, wn, grp, tig);
        if (it + 2 < nIter) ISSUE(it + 2);
        CP_COMMIT();
    }
    #undef ISSUE
}

// ---------------- persistent LSTM kernel ----------------
__global__ void __launch_bounds__(NTHR, 1)
lstm_persistent(const float* __restrict__ bih0, const float* __restrict__ bhh0,
                const float* __restrict__ bih1, const float* __restrict__ bhh1,
                float* __restrict__ out)
{
    extern __shared__ unsigned sh[];
    const unsigned sb = (unsigned)__cvta_generic_to_shared(sh);

    const int tid  = threadIdx.x;
    const int warp = tid >> 5, lane = tid & 31;
    const int grp  = lane >> 2, tig = lane & 3;
    const int wm   = warp >> 1, wn = warp & 1;
    const int mb = blockIdx.x & 1;        // batch block (2 x 64 rows)
    const int nb = blockIdx.x >> 1;       // 16-column block of j (0..63)

    const float* PB0 = g_wpack + (size_t)(0 * 64 + nb) * 65536;  // Wih0
    const float* PB1 = g_wpack + (size_t)(1 * 64 + nb) * 65536;  // Whh0
    const float* PB2 = g_wpack + (size_t)(2 * 64 + nb) * 65536;  // Wih1
    const float* PB3 = g_wpack + (size_t)(3 * 64 + nb) * 65536;  // Whh1

    float acc[4][4];
    float gx[4][4];        // layer-0 input gates + biases (time-constant)
    float b1r[4][2];       // layer-1 bias sums
    float c1r[4], c2r[4];
    #pragma unroll
    for (int i = 0; i < 4; i++) { c1r[i] = 0.0f; c2r[i] = 0.0f; }

    // prologue: gx = z @ Wih0^T + bih0 + bhh0
    gemm_phase(acc, g_z, g_z, PB0, PB0, 8, mb, sh, sb, tid, wm, wn, grp, tig);
    #pragma unroll
    for (int g = 0; g < 4; g++)
        #pragma unroll
        for (int r = 0; r < 4; r++) {
            int n = g * 1024 + nb * 16 + wn * 8 + 2 * tig + (r & 1);
            gx[g][r] = acc[g][r] + __ldg(bih0 + n) + __ldg(bhh0 + n);
        }
    #pragma unroll
    for (int g = 0; g < 4; g++)
        #pragma unroll
        for (int c = 0; c < 2; c++) {
            int n = g * 1024 + nb * 16 + wn * 8 + 2 * tig + c;
            b1r[g][c] = __ldg(bih1 + n) + __ldg(bhh1 + n);
        }

    const int rowb = mb * 64 + wm * 16 + grp;          // base batch row
    const int jb   = nb * 16 + wn * 8;                 // logical 8-col group base

    for (int t = 0; t < TT; t++) {
        const int q = t & 1, p = q ^ 1;

        // layer 0: h1_prev @ Whh0^T (+gx) -> h1[q], c1
        gemm_phase(acc, g_h1[p], g_h1[p], PB1, PB1, 8, mb, sh, sb,
                   tid, wm, wn, grp, tig);
        #pragma unroll
        for (int r = 0; r < 4; r++) {
            float si = acc[0][r] + gx[0][r];
            float sf = acc[1][r] + gx[1][r];
            float sg = acc[2][r] + gx[2][r];
            float so = acc[3][r] + gx[3][r];
            float cv = sigf(sf) * c1r[r] + sigf(si) * tanh_fast(sg);
            c1r[r] = cv;
            float h = sigf(so) * tanh_fast(cv);
            int row = rowb + ((r & 2) ? 8 : 0);
            int i3 = 2 * tig + (r & 1);
            __stcg(&g_h1[q][row * 1024 + jb + perm8(i3)], rtf(h));
        }

        grid_barrier();   // single per-timestep sync; slot parity covers other hazards

        // layer 1: [h1[q] | h2[p]] @ [Wih1 | Whh1]^T -> h2[q], c2, out
        gemm_phase(acc, g_h1[q], g_h2[p], PB2, PB3, 16, mb, sh, sb,
                   tid, wm, wn, grp, tig);
        #pragma unroll
        for (int r = 0; r < 4; r++) {
            float si = acc[0][r] + b1r[0][r & 1];
            float sf = acc[1][r] + b1r[1][r & 1];
            float sg = acc[2][r] + b1r[2][r & 1];
            float so = acc[3][r] + b1r[3][r & 1];
            float cv = sigf(sf) * c2r[r] + sigf(si) * tanh_fast(sg);
            c2r[r] = cv;
            float h = sigf(so) * tanh_fast(cv);
            int row = rowb + ((r & 2) ? 8 : 0);
            int i3 = 2 * tig + (r & 1);
            __stcg(&g_h2[q][row * 1024 + jb + perm8(i3)], rtf(h));
            out[((size_t)row * TT + t) * 1024 + jb + i3] = h;   // full-precision output
        }
    }
}

// ---------------- launch ----------------
extern "C" void kernel_launch(void* const* d_in, const int* in_sizes, int n_in,
                              void* d_out, int out_size) {
    const float* x    = (const float*)d_in[0];
    const float* fc_w = (const float*)d_in[1];
    const float* fc_b = (const float*)d_in[2];
    const float* Wih0 = (const float*)d_in[3];
    const float* Whh0 = (const float*)d_in[4];
    const float* bih0 = (const float*)d_in[5];
    const float* bhh0 = (const float*)d_in[6];
    const float* Wih1 = (const float*)d_in[7];
    const float* Whh1 = (const float*)d_in[8];
    const float* bih1 = (const float*)d_in[9];
    const float* bhh1 = (const float*)d_in[10];
    float* out = (float*)d_out;

    static int smem_set = 0;
    const int smem_bytes = NSTAGE * STAGE_B;   // 208896
    if (!smem_set) {
        cudaFuncSetAttribute(lstm_persistent,
                             cudaFuncAttributeMaxDynamicSharedMemorySize, smem_bytes);
        smem_set = 1;
    }

    init_zero_kernel<<<1024, 256>>>();
    pack_kernel<<<65536, 256>>>(Wih0, Whh0, Wih1, Whh1);
    fc_kernel<<<512, 256>>>(x, fc_w, fc_b);
    lstm_persistent<<<NBLK, NTHR, smem_bytes>>>(bih0, bhh0, bih1, bhh1, out);
}

// round 12
// speedup vs baseline: 1.5115x; 1.5115x over previous
#include <cuda_runtime.h>
#include <cstdint>

// Problem constants
#define BATCH 128
#define TT    512
#define NBLK  128      // persistent grid (all co-resident)
#define NTHR  256      // 8 warps: 4 tile-pairs (w, w+4) k-split over 32x32 warp tiles
#define SPITCH 72      // smem row pitch in words (72 % 32 == 8 -> conflict-free LDS.64)
#define TILEW  (64 * SPITCH)   // words per 64x64 tile buffer
#define NSTAGE 4

// ---------------- device scratch (static, allocation-free) ----------------
__device__ __align__(16) float g_z[BATCH * 1024];         // fc output (tf32, k-permuted)
__device__ __align__(16) float g_h1[2][BATCH * 1024];     // layer-0 hidden
__device__ __align__(16) float g_h2[2][BATCH * 1024];     // layer-1 hidden
__device__ __align__(16) float g_wpack[4 * 64 * 16 * 64 * 64];  // packed tf32 weights, 64MB
__device__ unsigned g_bar_count;
__device__ volatile unsigned g_bar_gen;

// permutation of the low-3 bits: pairs (k, k+4) adjacent -> LDS.64 fragment pairs
__device__ __host__ __forceinline__ int perm8(int i) { return ((i & 3) << 1) | ((i >> 2) & 1); }

// ---------------- helpers ----------------
__device__ __forceinline__ unsigned f2tf32(float x) {
    unsigned r;
    asm("cvt.rna.tf32.f32 %0, %1;" : "=r"(r) : "f"(x));
    return r;
}
__device__ __forceinline__ float rtf(float x) { return __uint_as_float(f2tf32(x)); }

__device__ __forceinline__ void mma_tf32(float c[4], unsigned a0, unsigned a1,
                                         unsigned a2, unsigned a3,
                                         unsigned b0, unsigned b1) {
    asm volatile(
        "mma.sync.aligned.m16n8k8.row.col.f32.tf32.tf32.f32 "
        "{%0,%1,%2,%3}, {%4,%5,%6,%7}, {%8,%9}, {%0,%1,%2,%3};"
        : "+f"(c[0]), "+f"(c[1]), "+f"(c[2]), "+f"(c[3])
        : "r"(a0), "r"(a1), "r"(a2), "r"(a3), "r"(b0), "r"(b1));
}

__device__ __forceinline__ void cp16(unsigned dst, const void* src) {
    asm volatile("cp.async.cg.shared.global [%0], [%1], 16;\n" :: "r"(dst), "l"(src));
}
#define CP_COMMIT() asm volatile("cp.async.commit_group;\n" ::: "memory")
#define CP_WAIT2()  asm volatile("cp.async.wait_group 2;\n" ::: "memory")

__device__ __forceinline__ float sigf(float x) { return 1.0f / (1.0f + __expf(-x)); }
__device__ __forceinline__ float tanh_fast(float x) {
    float e = __expf(2.0f * x);
    return 1.0f - 2.0f / (e + 1.0f);
}

// ---------------- software grid barrier ----------------
__device__ __forceinline__ void grid_barrier() {
    __threadfence();
    __syncthreads();
    if (threadIdx.x == 0) {
        unsigned gen = g_bar_gen;
        if (atomicAdd(&g_bar_count, 1u) == NBLK - 1) {
            *(volatile unsigned*)&g_bar_count = 0;
            __threadfence();
            g_bar_gen = gen + 1;
        } else {
            while (g_bar_gen == gen) {}
        }
        __threadfence();
    }
    __syncthreads();
}

// ---------------- init ----------------
__global__ void init_zero_kernel() {
    int idx = blockIdx.x * 256 + threadIdx.x;
    if (idx < BATCH * 1024 * 2) {
        (&g_h1[0][0])[idx] = 0.0f;
        (&g_h2[0][0])[idx] = 0.0f;
    }
    if (idx == 0) { g_bar_count = 0; g_bar_gen = 0; }
}

// ---------------- weight pre-pack: tf32, tile-native, k-permuted (R4 layout) --------
// wpack[mat][nb][kc16][rr64][kk64]; rr: gate=(rr>>3)&3, jloc=(rr&7)+((rr>>5)<<3)
__global__ void pack_kernel(const float* __restrict__ W0, const float* __restrict__ W1,
                            const float* __restrict__ W2, const float* __restrict__ W3) {
    int idx = blockIdx.x * 256 + threadIdx.x;   // 65536 blocks
    int kk  = idx & 63;
    int rr  = (idx >> 6) & 63;
    int kc  = (idx >> 12) & 15;
    int nb  = (idx >> 16) & 63;
    int mat = idx >> 22;
    const float* W = (mat == 0) ? W0 : (mat == 1) ? W1 : (mat == 2) ? W2 : W3;
    int gate = (rr >> 3) & 3;
    int jloc = (rr & 7) + ((rr >> 5) << 3);
    int srow = gate * 1024 + nb * 16 + jloc;
    float v = W[srow * 1024 + kc * 64 + kk];
    int kkp = (kk & ~7) | perm8(kk & 7);
    g_wpack[(((size_t)(mat * 64 + nb) * 16 + kc) << 12) + rr * 64 + kkp] = rtf(v);
}

// ---------------- fc: z = x @ fc_w^T + fc_b (tf32, k-permuted store) ----------------
__global__ void fc_kernel(const float* __restrict__ x, const float* __restrict__ fcw,
                          const float* __restrict__ fcb) {
    int idx = blockIdx.x * 256 + threadIdx.x;   // b*1024 + i
    int b = idx >> 10, i = idx & 1023;
    const float4* xr = reinterpret_cast<const float4*>(x + b * 256);
    const float4* wr = reinterpret_cast<const float4*>(fcw + i * 256);
    float s = fcb[i];
    #pragma unroll 8
    for (int o = 0; o < 64; o++) {
        float4 xv = __ldg(xr + o), wv = __ldg(wr + o);
        s += xv.x * wv.x + xv.y * wv.y + xv.z * wv.z + xv.w * wv.w;
    }
    int ip = (i & ~7) | perm8(i & 7);
    g_z[b * 1024 + ip] = rtf(s);
}

// ---------------- tile compute: warp 32x32 of CTA 64x64, half of k=64 ----------------
// par selects even (0) / odd (1) k8 groups: 4 of 8 groups per warp.
__device__ __forceinline__ void tile_compute(const unsigned* __restrict__ as,
                                             const unsigned* __restrict__ bs,
                                             float acc[2][4][4],
                                             int wm, int wn, int par,
                                             int grp, int tig) {
    const unsigned* pa = as + (wm * 32 + grp) * SPITCH + par * 8 + 2 * tig;
    const unsigned* pb = bs + (wn * 32 + grp) * SPITCH + par * 8 + 2 * tig;

    uint2 a[2][2], b[4];
    #pragma unroll
    for (int mi = 0; mi < 2; mi++) {
        a[mi][0] = *(const uint2*)(pa + mi * 16 * SPITCH);
        a[mi][1] = *(const uint2*)(pa + (mi * 16 + 8) * SPITCH);
    }
    #pragma unroll
    for (int nj = 0; nj < 4; nj++) b[nj] = *(const uint2*)(pb + nj * 8 * SPITCH);

    #pragma unroll
    for (int k8 = 0; k8 < 4; k8++) {
        uint2 na[2][2], nb2[4];
        if (k8 < 3) {
            const unsigned* qa = pa + (k8 + 1) * 16;
            const unsigned* qb = pb + (k8 + 1) * 16;
            #pragma unroll
            for (int mi = 0; mi < 2; mi++) {
                na[mi][0] = *(const uint2*)(qa + mi * 16 * SPITCH);
                na[mi][1] = *(const uint2*)(qa + (mi * 16 + 8) * SPITCH);
            }
            #pragma unroll
            for (int nj = 0; nj < 4; nj++) nb2[nj] = *(const uint2*)(qb + nj * 8 * SPITCH);
        }
        #pragma unroll
        for (int mi = 0; mi < 2; mi++)
            #pragma unroll
            for (int nj = 0; nj < 4; nj++)
                mma_tf32(acc[mi][nj], a[mi][0].x, a[mi][1].x, a[mi][0].y, a[mi][1].y,
                         b[nj].x, b[nj].y);
        if (k8 < 3) {
            #pragma unroll
            for (int mi = 0; mi < 2; mi++) { a[mi][0] = na[mi][0]; a[mi][1] = na[mi][1]; }
            #pragma unroll
            for (int nj = 0; nj < 4; nj++) b[nj] = nb2[nj];
        }
    }
}

// ---------------- GEMM phase: partial acc += A[64 x 64*nIter] @ Bpacked^T ----------------
__device__ __forceinline__ void gemm_phase(
    float acc[2][4][4],
    const float* __restrict__ A0, const float* __restrict__ A1,
    const float* __restrict__ B0, const float* __restrict__ B1,
    int nIter, int mb, unsigned* As, unsigned* Bs,
    unsigned AsBase, unsigned BsBase,
    int tid, int wm, int wn, int par, int grp, int tig)
{
    #pragma unroll
    for (int mi = 0; mi < 2; mi++)
        #pragma unroll
        for (int nj = 0; nj < 4; nj++)
            #pragma unroll
            for (int r = 0; r < 4; r++) acc[mi][nj][r] = 0.0f;

    const int lrow = tid >> 4;            // 0..15 base row, +16 per v
    const int c4   = (tid & 15) << 2;     // 0..60

    #define ISSUE(s) do {                                                           \
        const float* A_  = ((s) < 16) ? A0 : A1;                                    \
        const float* Bt_ = (((s) < 16) ? B0 : B1) + (((s) & 15) << 12);             \
        int kk_ = ((s) * 64) & 1023;                                                \
        unsigned so_ = ((s) & 3) * (TILEW * 4);                                     \
        _Pragma("unroll")                                                           \
        for (int v = 0; v < 4; v++) {                                               \
            int row = lrow + v * 16;                                                \
            cp16(AsBase + so_ + (row * SPITCH + c4) * 4,                            \
                 A_ + (mb * 64 + row) * 1024 + kk_ + c4);                           \
            cp16(BsBase + so_ + (row * SPITCH + c4) * 4, Bt_ + row * 64 + c4);      \
        }                                                                           \
    } while (0)

    ISSUE(0); CP_COMMIT();
    ISSUE(1); CP_COMMIT();
    ISSUE(2); CP_COMMIT();

    for (int it = 0; it < nIter; it++) {
        CP_WAIT2();
        __syncthreads();
        tile_compute(As + (it & 3) * TILEW, Bs + (it & 3) * TILEW,
                     acc, wm, wn, par, grp, tig);
        if (it + 3 < nIter) ISSUE(it + 3);
        CP_COMMIT();
    }
    #undef ISSUE
}

// ---------------- pair reduction: acc(warp w) += acc(warp w+4) through smem --------
__device__ __forceinline__ void pair_reduce(float acc[2][4][4], float* red,
                                            int warp, int lane) {
    float* base = red + ((warp & 3) * 32 + lane) * 36;
    if (warp >= 4) {
        #pragma unroll
        for (int mi = 0; mi < 2; mi++)
            #pragma unroll
            for (int nj = 0; nj < 4; nj++)
                *reinterpret_cast<float4*>(base + mi * 16 + nj * 4) =
                    *reinterpret_cast<const float4*>(acc[mi][nj]);
    }
    __syncthreads();
    if (warp < 4) {
        #pragma unroll
        for (int mi = 0; mi < 2; mi++)
            #pragma unroll
            for (int nj = 0; nj < 4; nj++) {
                float4 v = *reinterpret_cast<const float4*>(base + mi * 16 + nj * 4);
                acc[mi][nj][0] += v.x; acc[mi][nj][1] += v.y;
                acc[mi][nj][2] += v.z; acc[mi][nj][3] += v.w;
            }
    }
}

// ---------------- persistent LSTM kernel ----------------
__global__ void __launch_bounds__(NTHR, 1)
lstm_persistent(const float* __restrict__ bih0, const float* __restrict__ bhh0,
                const float* __restrict__ bih1, const float* __restrict__ bhh1,
                float* __restrict__ out)
{
    extern __shared__ unsigned sh[];
    unsigned* As = sh;
    unsigned* Bs = sh + NSTAGE * TILEW;
    float* red   = reinterpret_cast<float*>(sh + 2 * NSTAGE * TILEW);
    const unsigned AsBase = (unsigned)__cvta_generic_to_shared(As);
    const unsigned BsBase = (unsigned)__cvta_generic_to_shared(Bs);

    const int tid  = threadIdx.x;
    const int warp = tid >> 5, lane = tid & 31;
    const int grp  = lane >> 2, tig = lane & 3;
    const int wm   = (warp >> 1) & 1, wn = warp & 1, par = warp >> 2;
    const int mb = blockIdx.x & 1;        // batch block (2 x 64 rows)
    const int nb = blockIdx.x >> 1;       // 16-column block of j (0..63)

    const float* PB0 = g_wpack + (size_t)(0 * 64 + nb) * 65536;  // Wih0
    const float* PB1 = g_wpack + (size_t)(1 * 64 + nb) * 65536;  // Whh0
    const float* PB2 = g_wpack + (size_t)(2 * 64 + nb) * 65536;  // Wih1
    const float* PB3 = g_wpack + (size_t)(3 * 64 + nb) * 65536;  // Whh1

    float acc[2][4][4];
    float gx[2][4][4];     // layer-0 input gates + biases (time-constant, warps 0-3)
    float b1r[4][2];       // layer-1 bias sums
    float c1r[8], c2r[8];
    #pragma unroll
    for (int i = 0; i < 8; i++) { c1r[i] = 0.0f; c2r[i] = 0.0f; }

    // prologue: gx = z @ Wih0^T + bih0 + bhh0
    gemm_phase(acc, g_z, g_z, PB0, PB0, 16, mb, As, Bs, AsBase, BsBase,
               tid, wm, wn, par, grp, tig);
    pair_reduce(acc, red, warp, lane);
    if (warp < 4) {
        #pragma unroll
        for (int mi = 0; mi < 2; mi++)
            #pragma unroll
            for (int g = 0; g < 4; g++)
                #pragma unroll
                for (int r = 0; r < 4; r++) {
                    int n = g * 1024 + nb * 16 + wn * 8 + 2 * tig + (r & 1);
                    gx[mi][g][r] = acc[mi][g][r] + __ldg(bih0 + n) + __ldg(bhh0 + n);
                }
        #pragma unroll
        for (int g = 0; g < 4; g++)
            #pragma unroll
            for (int c = 0; c < 2; c++) {
                int n = g * 1024 + nb * 16 + wn * 8 + 2 * tig + c;
                b1r[g][c] = __ldg(bih1 + n) + __ldg(bhh1 + n);
            }
    }

    const int rowb = mb * 64 + wm * 32 + grp;          // base batch row (warps 0-3)
    const int jb   = nb * 16 + wn * 8;                 // logical 8-col group base

    for (int t = 0; t < TT; t++) {
        const int q = t & 1, p = q ^ 1;

        // layer 0: h1_prev @ Whh0^T (+gx) -> h1[q], c1
        gemm_phase(acc, g_h1[p], g_h1[p], PB1, PB1, 16, mb, As, Bs, AsBase, BsBase,
                   tid, wm, wn, par, grp, tig);
        pair_reduce(acc, red, warp, lane);
        if (warp < 4) {
            #pragma unroll
            for (int mi = 0; mi < 2; mi++)
                #pragma unroll
                for (int r = 0; r < 4; r++) {
                    float si = acc[mi][0][r] + gx[mi][0][r];
                    float sf = acc[mi][1][r] + gx[mi][1][r];
                    float sg = acc[mi][2][r] + gx[mi][2][r];
                    float so = acc[mi][3][r] + gx[mi][3][r];
                    int cell = mi * 4 + r;
                    float cv = sigf(sf) * c1r[cell] + sigf(si) * tanh_fast(sg);
                    c1r[cell] = cv;
                    float h = sigf(so) * tanh_fast(cv);
                    int row = rowb + mi * 16 + ((r & 2) ? 8 : 0);
                    int i3 = 2 * tig + (r & 1);
                    __stcg(&g_h1[q][row * 1024 + jb + perm8(i3)], rtf(h));
                }
        }

        grid_barrier();   // single per-timestep sync; slot parity covers other hazards

        // layer 1: [h1[q] | h2[p]] @ [Wih1 | Whh1]^T -> h2[q], c2, out
        gemm_phase(acc, g_h1[q], g_h2[p], PB2, PB3, 32, mb, As, Bs, AsBase, BsBase,
                   tid, wm, wn, par, grp, tig);
        pair_reduce(acc, red, warp, lane);
        if (warp < 4) {
            #pragma unroll
            for (int mi = 0; mi < 2; mi++)
                #pragma unroll
                for (int r = 0; r < 4; r++) {
                    float si = acc[mi][0][r] + b1r[0][r & 1];
                    float sf = acc[mi][1][r] + b1r[1][r & 1];
                    float sg = acc[mi][2][r] + b1r[2][r & 1];
                    float so = acc[mi][3][r] + b1r[3][r & 1];
                    int cell = mi * 4 + r;
                    float cv = sigf(sf) * c2r[cell] + sigf(si) * tanh_fast(sg);
                    c2r[cell] = cv;
                    float h = sigf(so) * tanh_fast(cv);
                    int row = rowb + mi * 16 + ((r & 2) ? 8 : 0);
                    int i3 = 2 * tig + (r & 1);
                    __stcg(&g_h2[q][row * 1024 + jb + perm8(i3)], rtf(h));
                    out[((size_t)row * TT + t) * 1024 + jb + i3] = h;  // fp32 output
                }
        }
    }
}

// ---------------- launch ----------------
extern "C" void kernel_launch(void* const* d_in, const int* in_sizes, int n_in,
                              void* d_out, int out_size) {
    const float* x    = (const float*)d_in[0];
    const float* fc_w = (const float*)d_in[1];
    const float* fc_b = (const float*)d_in[2];
    const float* Wih0 = (const float*)d_in[3];
    const float* Whh0 = (const float*)d_in[4];
    const float* bih0 = (const float*)d_in[5];
    const float* bhh0 = (const float*)d_in[6];
    const float* Wih1 = (const float*)d_in[7];
    const float* Whh1 = (const float*)d_in[8];
    const float* bih1 = (const float*)d_in[9];
    const float* bhh1 = (const float*)d_in[10];
    float* out = (float*)d_out;

    static int smem_set = 0;
    const int smem_bytes = 2 * NSTAGE * TILEW * 4 + 128 * 36 * 4;   // 147456 + 18432
    if (!smem_set) {
        cudaFuncSetAttribute(lstm_persistent,
                             cudaFuncAttributeMaxDynamicSharedMemorySize, smem_bytes);
        smem_set = 1;
    }

    init_zero_kernel<<<1024, 256>>>();
    pack_kernel<<<65536, 256>>>(Wih0, Whh0, Wih1, Whh1);
    fc_kernel<<<512, 256>>>(x, fc_w, fc_b);
    lstm_persistent<<<NBLK, NTHR, smem_bytes>>>(bih0, bhh0, bih1, bhh1, out);
}